// round 12
// baseline (speedup 1.0000x reference)
#include <cuda_runtime.h>
#include <math.h>
#include <stdint.h>

#define TLEN  500
#define BATCH 32
#define DIN   1024
#define HID   1024
#define NT    4096      // 4 gates * HID
#define GRID_REC 128
#define REC_THREADS 512

// ---------------- rec_persist smem layout (floats) ----------------
#define WSTR  1028
#define SW_F  (32 * WSTR)
#define SH_F  (32 * 260)
#define SRED_F (3 * 128 * 8)
#define SH_OFF  SW_F
#define SRED_OFF (SW_F + SH_F)
#define SMEM_BYTES ((SW_F + SH_F + SRED_F) * 4)

// ---------------- sgemm_pre_tc smem layout (floats) ----------------
#define SGA_STR 36                    // A row stride (conflict-free frag loads)
#define SGB_STR 136                   // B row stride (conflict-free frag loads)
#define SG_A_F  (128 * SGA_STR)       // 4608
#define SG_B_F  (32 * SGB_STR)        // 4352
#define SG_BUF_F (SG_A_F + 2 * SG_B_F)  // 13312 floats per buffer
#define SG_SMEM_BYTES (2 * SG_BUF_F * 4) // 106496 B double-buffered
#define SG_THREADS 512

typedef unsigned long long ull;

__device__ __forceinline__ void ffma2(ull& d, ull a, ull b) {
    asm("fma.rn.f32x2 %0, %1, %2, %0;" : "+l"(d) : "l"(a), "l"(b));
}
__device__ __forceinline__ float2 u2f(ull u) {
    float2 r; asm("mov.b64 {%0,%1}, %2;" : "=f"(r.x), "=f"(r.y) : "l"(u)); return r;
}
__device__ __forceinline__ uint32_t f2tf32(float v) {
    uint32_t u; asm("cvt.rna.tf32.f32 %0, %1;" : "=r"(u) : "f"(v)); return u;
}
__device__ __forceinline__ void mma_tf32(float* c, const uint32_t* a, const uint32_t* b) {
    asm("mma.sync.aligned.m16n8k8.row.col.f32.tf32.tf32.f32 "
        "{%0,%1,%2,%3},{%4,%5,%6,%7},{%8,%9},{%0,%1,%2,%3};"
        : "+f"(c[0]), "+f"(c[1]), "+f"(c[2]), "+f"(c[3])
        : "r"(a[0]), "r"(a[1]), "r"(a[2]), "r"(a[3]), "r"(b[0]), "r"(b[1]));
}
__device__ __forceinline__ void cpa16(uint32_t saddr, const void* g) {
    asm volatile("cp.async.cg.shared.global [%0], [%1], 16;" :: "r"(saddr), "l"(g));
}

// ---------------- device-global scratch ----------------
__device__ __align__(16) float g_wxB_hi[(size_t)DIN * NT];            // tf32 hi, 16 MB
__device__ __align__(16) float g_wxB_lo[(size_t)DIN * NT];            // tf32 lo, 16 MB
__device__ __align__(16) float g_whT[(size_t)NT * HID];               // [(h*4+g)][d] 16 MB
__device__ __align__(16) float g_pre[(size_t)TLEN * 4 * BATCH * HID]; // [t][g][b][h] 262 MB
__device__ __align__(16) float g_h2[2][BATCH * HID];
__device__ volatile unsigned g_gen;
__device__ unsigned g_cnt;

// quaternion cat tables
__constant__ int   c_qidx[16] = {0,1,2,3,  1,0,3,2,  2,3,0,1,  3,2,1,0};
__constant__ float c_qsgn[16] = { 1.f, 1.f, 1.f, 1.f,
                                 -1.f, 1.f, 1.f,-1.f,
                                 -1.f,-1.f, 1.f, 1.f,
                                 -1.f, 1.f,-1.f, 1.f};

// ---------------- weight expansion (+ tf32 hi/lo split for wx) ----------------
__global__ void expand_weights(const float* __restrict__ wx, const float* __restrict__ wh) {
    int i = blockIdx.x * 256 + threadIdx.x;
    int half = i >> 22;
    int o = i & 4194303;
    if (half == 0) {
        int d = o >> 12, n = o & 4095;
        int g = n >> 10, ho = n & 1023;
        int e = ho >> 8, hh = ho & 255;
        int c = d >> 8,  dd = d & 255;
        int q = c * 4 + e;
        float v = c_qsgn[q] * wx[((g * 4 + c_qidx[q]) * 256 + dd) * 256 + hh];
        uint32_t hb = f2tf32(v);
        float hf = __uint_as_float(hb);
        uint32_t lb = f2tf32(v - hf);
        g_wxB_hi[o] = hf;
        g_wxB_lo[o] = __uint_as_float(lb);
    } else {
        int h = o >> 12, g = (o >> 10) & 3, d = o & 1023;
        int e = h >> 8, hh = h & 255;
        int c = d >> 8, dd = d & 255;
        int q = c * 4 + e;
        g_whT[o] = c_qsgn[q] * wh[((g * 4 + c_qidx[q]) * 256 + dd) * 256 + hh];
    }
}

__global__ void zero_state() {
    int i = blockIdx.x * 256 + threadIdx.x;
    if (i < BATCH * HID) g_h2[0][i] = 0.f;
}

// ---------------- input GEMM on tensor cores (3xTF32), 512 threads ----------------
// Block 128(m)x128(n), K-step 32, 16 warps each m32xn32 (2 mi x 4 ni),
// cp.async double buffer. 16 warps/SM hides LDS->CVT->MMA latency chains.
__global__ __launch_bounds__(SG_THREADS) void sgemm_pre_tc(const float* __restrict__ x,
                                                           const float* __restrict__ bx) {
    extern __shared__ float sm[];
    const int bn = blockIdx.x;      // 0..31
    const int bm = blockIdx.y;      // 0..124
    const int tid = threadIdx.x;
    const int lane = tid & 31;
    const int wid = tid >> 5;       // 0..15
    const int wm = wid & 3;         // 0..3  (m quadrant of 32)
    const int wn = wid >> 2;        // 0..3  (n quadrant of 32)
    const int r  = lane >> 2;       // 0..7
    const int cq = lane & 3;        // 0..3

    float acc[2][4][4];
#pragma unroll
    for (int mi = 0; mi < 2; mi++)
#pragma unroll
        for (int ni = 0; ni < 4; ni++)
#pragma unroll
            for (int q = 0; q < 4; q++) acc[mi][ni][q] = 0.f;

    const uint32_t sm0 = (uint32_t)__cvta_generic_to_shared(sm);

    auto load_tile = [&](int kt, int buf) {
        uint32_t Ab = sm0 + (buf * SG_BUF_F) * 4;
        uint32_t Bh = Ab + SG_A_F * 4;
        uint32_t Bl = Bh + SG_B_F * 4;
        const float* xg = x + (size_t)(bm * 128) * DIN + kt;
        const float* wh = g_wxB_hi + (size_t)kt * NT + bn * 128;
        const float* wl = g_wxB_lo + (size_t)kt * NT + bn * 128;
#pragma unroll
        for (int q = 0; q < 2; q++) {
            int idx = tid + SG_THREADS * q;       // 0..1023
            int arow = idx >> 3, ac4 = idx & 7;   // A: 128 x 8 float4
            cpa16(Ab + (arow * SGA_STR + ac4 * 4) * 4, xg + (size_t)arow * DIN + ac4 * 4);
            int brow = idx >> 5, bc4 = idx & 31;  // B: 32 x 32 float4
            cpa16(Bh + (brow * SGB_STR + bc4 * 4) * 4, wh + (size_t)brow * NT + bc4 * 4);
            cpa16(Bl + (brow * SGB_STR + bc4 * 4) * 4, wl + (size_t)brow * NT + bc4 * 4);
        }
    };

    load_tile(0, 0);
    asm volatile("cp.async.commit_group;");

    for (int t = 0; t < 32; t++) {
        if (t < 31) {
            load_tile((t + 1) * 32, (t + 1) & 1);
            asm volatile("cp.async.commit_group;");
            asm volatile("cp.async.wait_group 1;");
        } else {
            asm volatile("cp.async.wait_group 0;");
        }
        __syncthreads();

        const float* As = sm + (t & 1) * SG_BUF_F;
        const float* Bh = As + SG_A_F;
        const float* Bl = Bh + SG_B_F;

#pragma unroll
        for (int kf = 0; kf < 4; kf++) {
            const int k0 = kf * 8;
            uint32_t bh[4][2], bl[4][2];
            const int brow = k0 + cq;
#pragma unroll
            for (int ni = 0; ni < 4; ni++) {
                int cb = wn * 32 + ni * 8 + r;
                bh[ni][0] = __float_as_uint(Bh[brow * SGB_STR + cb]);
                bh[ni][1] = __float_as_uint(Bh[(brow + 4) * SGB_STR + cb]);
                bl[ni][0] = __float_as_uint(Bl[brow * SGB_STR + cb]);
                bl[ni][1] = __float_as_uint(Bl[(brow + 4) * SGB_STR + cb]);
            }
#pragma unroll
            for (int mi = 0; mi < 2; mi++) {
                int rb = wm * 32 + mi * 16 + r;
                float v0 = As[rb * SGA_STR + k0 + cq];
                float v1 = As[(rb + 8) * SGA_STR + k0 + cq];
                float v2 = As[rb * SGA_STR + k0 + cq + 4];
                float v3 = As[(rb + 8) * SGA_STR + k0 + cq + 4];
                uint32_t ahi[4], alo[4];
                ahi[0] = f2tf32(v0); alo[0] = f2tf32(v0 - __uint_as_float(ahi[0]));
                ahi[1] = f2tf32(v1); alo[1] = f2tf32(v1 - __uint_as_float(ahi[1]));
                ahi[2] = f2tf32(v2); alo[2] = f2tf32(v2 - __uint_as_float(ahi[2]));
                ahi[3] = f2tf32(v3); alo[3] = f2tf32(v3 - __uint_as_float(ahi[3]));
#pragma unroll
                for (int ni = 0; ni < 4; ni++) {
                    mma_tf32(acc[mi][ni], ahi, bh[ni]);
                    mma_tf32(acc[mi][ni], ahi, bl[ni]);
                    mma_tf32(acc[mi][ni], alo, bh[ni]);
                }
            }
        }
        __syncthreads();
    }

    // epilogue: add bias, scatter to g_pre[t][g][b][h]
#pragma unroll
    for (int ni = 0; ni < 4; ni++) {
        int n0 = bn * 128 + wn * 32 + ni * 8 + 2 * cq;
        int g = n0 >> 10, h = n0 & 1023;
        float2 bb = *(const float2*)(bx + n0);
#pragma unroll
        for (int mi = 0; mi < 2; mi++) {
            int m0 = bm * 128 + wm * 32 + mi * 16 + r;
            int t0 = m0 >> 5, b0 = m0 & 31;
            int m1 = m0 + 8;
            int t1 = m1 >> 5, b1 = m1 & 31;
            float2 o0 = make_float2(acc[mi][ni][0] + bb.x, acc[mi][ni][1] + bb.y);
            float2 o1 = make_float2(acc[mi][ni][2] + bb.x, acc[mi][ni][3] + bb.y);
            *(float2*)&g_pre[(((size_t)t0 * 4 + g) * 32 + b0) * 1024 + h] = o0;
            *(float2*)&g_pre[(((size_t)t1 * 4 + g) * 32 + b1) * 1024 + h] = o1;
        }
    }
}

// ---------------- software grid barrier ----------------
__device__ __forceinline__ void grid_bar() {
    __syncthreads();
    if (threadIdx.x == 0) {
        __threadfence();
        unsigned gen = g_gen;
        if (atomicAdd(&g_cnt, 1) == GRID_REC - 1) {
            g_cnt = 0;
            __threadfence();
            g_gen = gen + 1;
        } else {
            while (g_gen == gen) {}
        }
        __threadfence();
    }
    __syncthreads();
}

// ---------------- persistent recurrence (f32x2, k-paired) — unchanged (passing) ----------------
__global__ __launch_bounds__(REC_THREADS, 1) void rec_persist(float* __restrict__ out) {
    extern __shared__ float smem[];
    const int hs  = blockIdx.x;
    const int tid = threadIdx.x;
    const int w   = tid >> 5;
    const int ks  = w >> 2;
    const int whlp = w & 3;
    const int l   = tid & 31;
    const int hp  = l >> 4;
    const int b16 = l & 15;
    const int rg  = whlp * 2 + hp;
    const int b0  = b16, b1 = b16 + 16;
    const int rloc = whlp * 32 + l;

#pragma unroll
    for (int q = 0; q < 16; q++) {
        int i4 = tid + REC_THREADS * q;
        int lrr = i4 >> 8, kq = i4 & 255;
        *(float4*)&smem[lrr * WSTR + kq * 4] =
            *(const float4*)(g_whT + (size_t)(hs * 32 + lrr) * 1024 + kq * 4);
    }
    __syncthreads();

    float creg[2] = {0.f, 0.f};

    for (int t = 0; t < TLEN; t++) {
        const float* hc = g_h2[t & 1];

        float pg[4][2];
        if (ks == 0) {
            const float* pt = g_pre + (size_t)t * 131072 + hs * 8 + rg;
#pragma unroll
            for (int g = 0; g < 4; g++) {
                pg[g][0] = __ldcg(pt + g * 32768 + b0 * 1024);
                pg[g][1] = __ldcg(pt + g * 32768 + b1 * 1024);
            }
        }

        ull acc[4][2];
#pragma unroll
        for (int g = 0; g < 4; g++) { acc[g][0] = 0ull; acc[g][1] = 0ull; }

        float4 pf[4];
#pragma unroll
        for (int q = 0; q < 4; q++) {
            int f = tid + REC_THREADS * q;
            pf[q] = __ldcg((const float4*)(hc + (f >> 6) * 1024 + (f & 63) * 4));
        }

        for (int c = 0; c < 4; c++) {
#pragma unroll
            for (int q = 0; q < 4; q++) {
                int f = tid + REC_THREADS * q;
                *(float4*)&smem[SH_OFF + (f >> 6) * 260 + (f & 63) * 4] = pf[q];
            }
            __syncthreads();
            if (c < 3) {
#pragma unroll
                for (int q = 0; q < 4; q++) {
                    int f = tid + REC_THREADS * q;
                    pf[q] = __ldcg((const float4*)(hc + (f >> 6) * 1024 + (c + 1) * 256 + (f & 63) * 4));
                }
            }
            const float* wb  = &smem[rg * 4 * WSTR + c * 256 + ks * 64];
            const float* hr0 = &smem[SH_OFF + b0 * 260 + ks * 64];
            const float* hr1 = &smem[SH_OFF + b1 * 260 + ks * 64];
#pragma unroll
            for (int kk = 0; kk < 64; kk += 4) {
                ulonglong2 H0 = *(const ulonglong2*)(hr0 + kk);
                ulonglong2 H1 = *(const ulonglong2*)(hr1 + kk);
#pragma unroll
                for (int g = 0; g < 4; g++) {
                    ulonglong2 W = *(const ulonglong2*)(wb + g * WSTR + kk);
                    ffma2(acc[g][0], W.x, H0.x);
                    ffma2(acc[g][0], W.y, H0.y);
                    ffma2(acc[g][1], W.x, H1.x);
                    ffma2(acc[g][1], W.y, H1.y);
                }
            }
            __syncthreads();
        }

        float s[4][2];
#pragma unroll
        for (int g = 0; g < 4; g++) {
            float2 p0 = u2f(acc[g][0]); s[g][0] = p0.x + p0.y;
            float2 p1 = u2f(acc[g][1]); s[g][1] = p1.x + p1.y;
        }

        if (ks > 0) {
            float4* dst = (float4*)&smem[SRED_OFF + ((ks - 1) * 128 + rloc) * 8];
            dst[0] = make_float4(s[0][0], s[1][0], s[2][0], s[3][0]);
            dst[1] = make_float4(s[0][1], s[1][1], s[2][1], s[3][1]);
        }
        __syncthreads();

        if (ks == 0) {
#pragma unroll
            for (int q = 0; q < 3; q++) {
                const float4* src = (const float4*)&smem[SRED_OFF + (q * 128 + rloc) * 8];
                float4 v0 = src[0], v1 = src[1];
                s[0][0] += v0.x; s[1][0] += v0.y; s[2][0] += v0.z; s[3][0] += v0.w;
                s[0][1] += v1.x; s[1][1] += v1.y; s[2][1] += v1.z; s[3][1] += v1.w;
            }
#pragma unroll
            for (int j = 0; j < 2; j++) {
                float g0 = s[0][j] + pg[0][j];
                float g1 = s[1][j] + pg[1][j];
                float g2 = s[2][j] + pg[2][j];
                float g3 = s[3][j] + pg[3][j];
                float f = 1.f / (1.f + __expf(-g0));
                float i = 1.f / (1.f + __expf(-g1));
                float o = 1.f / (1.f + __expf(-g2));
                creg[j] = i * tanhf(g3) + f * creg[j];
                float hn = o * tanhf(creg[j]);
                int b = (j == 0) ? b0 : b1;
                int pidx = b * 1024 + hs * 8 + rg;
                g_h2[(t + 1) & 1][pidx] = hn;
                out[(size_t)t * (BATCH * HID) + pidx] = hn;
            }
        }

        grid_bar();
    }
}

// ---------------- launch: 4 graph nodes ----------------
extern "C" void kernel_launch(void* const* d_in, const int* in_sizes, int n_in,
                              void* d_out, int out_size) {
    const float* x  = (const float*)d_in[0];   // [500][32][1024]
    const float* wx = (const float*)d_in[1];   // [4][4][256][256]
    const float* wh = (const float*)d_in[2];   // [4][4][256][256]
    const float* bx = (const float*)d_in[3];   // [4][1024]
    float* out = (float*)d_out;                // [500][32][1024]

    cudaFuncSetAttribute(sgemm_pre_tc, cudaFuncAttributeMaxDynamicSharedMemorySize, SG_SMEM_BYTES);
    cudaFuncSetAttribute(rec_persist, cudaFuncAttributeMaxDynamicSharedMemorySize, SMEM_BYTES);

    expand_weights<<<32768, 256>>>(wx, wh);
    zero_state<<<128, 256>>>();
    sgemm_pre_tc<<<dim3(32, 125), SG_THREADS, SG_SMEM_BYTES>>>(x, bx);
    rec_persist<<<GRID_REC, REC_THREADS, SMEM_BYTES>>>(out);
}

// round 13
// speedup vs baseline: 1.0910x; 1.0910x over previous
#include <cuda_runtime.h>
#include <cuda_bf16.h>
#include <math.h>
#include <stdint.h>

#define TLEN  500
#define BATCH 32
#define DIN   1024
#define HID   1024
#define NT    4096      // 4 gates * HID
#define GRID_REC 128
#define REC_THREADS 512

// ---------------- rec_persist smem layout (floats) ----------------
#define WSTR  1028
#define SW_F  (32 * WSTR)
#define SH_F  (32 * 260)
#define SRED_F (3 * 128 * 8)
#define SH_OFF  SW_F
#define SRED_OFF (SW_F + SH_F)
#define SMEM_BYTES ((SW_F + SH_F + SRED_F) * 4)

// ---------------- sgemm_pre_tc smem layout (bytes) ----------------
#define SGA_STR 36                      // A row stride in floats
#define SGB_STR 40                      // B row stride in bf16 (banks: 20r+cq all distinct)
#define SG_A_B  (128 * SGA_STR * 4)     // 18432 B
#define SG_B_B  (128 * SGB_STR * 2)     // 10240 B
#define SG_BUF_B (SG_A_B + 2 * SG_B_B)  // 38912 B per buffer
#define SG_SMEM_BYTES (2 * SG_BUF_B)    // 77824 B double-buffered
#define SG_THREADS 512

typedef unsigned long long ull;

__device__ __forceinline__ void ffma2(ull& d, ull a, ull b) {
    asm("fma.rn.f32x2 %0, %1, %2, %0;" : "+l"(d) : "l"(a), "l"(b));
}
__device__ __forceinline__ float2 u2f(ull u) {
    float2 r; asm("mov.b64 {%0,%1}, %2;" : "=f"(r.x), "=f"(r.y) : "l"(u)); return r;
}
// pack two f32 -> bf16x2; k_even lands in LOWER 16 bits (first PTX src = upper half)
__device__ __forceinline__ uint32_t packbf(float k_even, float k_odd) {
    uint32_t d;
    asm("cvt.rn.bf16x2.f32 %0, %1, %2;" : "=r"(d) : "f"(k_odd), "f"(k_even));
    return d;
}
__device__ __forceinline__ void mma_bf16(float* c, const uint32_t* a, const uint32_t* b) {
    asm("mma.sync.aligned.m16n8k16.row.col.f32.bf16.bf16.f32 "
        "{%0,%1,%2,%3},{%4,%5,%6,%7},{%8,%9},{%0,%1,%2,%3};"
        : "+f"(c[0]), "+f"(c[1]), "+f"(c[2]), "+f"(c[3])
        : "r"(a[0]), "r"(a[1]), "r"(a[2]), "r"(a[3]), "r"(b[0]), "r"(b[1]));
}
__device__ __forceinline__ void cpa16(uint32_t saddr, const void* g) {
    asm volatile("cp.async.cg.shared.global [%0], [%1], 16;" :: "r"(saddr), "l"(g));
}

// ---------------- device-global scratch ----------------
__device__ __align__(16) __nv_bfloat16 g_wxB_hi[(size_t)NT * DIN];    // [n][d] bf16 hi, 8 MB
__device__ __align__(16) __nv_bfloat16 g_wxB_lo[(size_t)NT * DIN];    // [n][d] bf16 lo, 8 MB
__device__ __align__(16) float g_whT[(size_t)NT * HID];               // [(h*4+g)][d] 16 MB
__device__ __align__(16) float g_pre[(size_t)TLEN * 4 * BATCH * HID]; // [t][g][b][h] 262 MB
__device__ __align__(16) float g_h2[2][BATCH * HID];
__device__ volatile unsigned g_gen;
__device__ unsigned g_cnt;

// quaternion cat tables
__constant__ int   c_qidx[16] = {0,1,2,3,  1,0,3,2,  2,3,0,1,  3,2,1,0};
__constant__ float c_qsgn[16] = { 1.f, 1.f, 1.f, 1.f,
                                 -1.f, 1.f, 1.f,-1.f,
                                 -1.f,-1.f, 1.f, 1.f,
                                 -1.f, 1.f,-1.f, 1.f};

// ---------------- weight expansion (+ bf16 hi/lo split for wx, [n][d] layout) ----------------
__global__ void expand_weights(const float* __restrict__ wx, const float* __restrict__ wh) {
    int i = blockIdx.x * 256 + threadIdx.x;
    int half = i >> 22;
    int o = i & 4194303;
    if (half == 0) {
        int n = o >> 10, d = o & 1023;       // o = n*1024 + d
        int g = n >> 10, ho = n & 1023;
        int e = ho >> 8, hh = ho & 255;
        int c = d >> 8,  dd = d & 255;
        int q = c * 4 + e;
        float v = c_qsgn[q] * wx[((g * 4 + c_qidx[q]) * 256 + dd) * 256 + hh];
        __nv_bfloat16 hb = __float2bfloat16(v);
        float hf = __bfloat162float(hb);
        g_wxB_hi[o] = hb;
        g_wxB_lo[o] = __float2bfloat16(v - hf);
    } else {
        int h = o >> 12, g = (o >> 10) & 3, d = o & 1023;
        int e = h >> 8, hh = h & 255;
        int c = d >> 8, dd = d & 255;
        int q = c * 4 + e;
        g_whT[o] = c_qsgn[q] * wh[((g * 4 + c_qidx[q]) * 256 + dd) * 256 + hh];
    }
}

__global__ void zero_state() {
    int i = blockIdx.x * 256 + threadIdx.x;
    if (i < BATCH * HID) g_h2[0][i] = 0.f;
}

// ---------------- input GEMM on tensor cores (3x BF16 split), 512 threads ----------------
// Block 128(m)x128(n), K-step 32, 16 warps each m32xn32 (2 mi x 4 ni), mma.m16n8k16.
// Weights pre-split bf16 hi/lo in [n][k]; x split at fragment time.
__global__ __launch_bounds__(SG_THREADS) void sgemm_pre_tc(const float* __restrict__ x,
                                                           const float* __restrict__ bx) {
    extern __shared__ char smc[];
    const int bn = blockIdx.x;      // 0..31
    const int bm = blockIdx.y;      // 0..124
    const int tid = threadIdx.x;
    const int lane = tid & 31;
    const int wid = tid >> 5;       // 0..15
    const int wm = wid & 3;         // m quadrant of 32
    const int wn = wid >> 2;        // n quadrant of 32
    const int r  = lane >> 2;       // 0..7
    const int cq = lane & 3;        // 0..3

    float acc[2][4][4];
#pragma unroll
    for (int mi = 0; mi < 2; mi++)
#pragma unroll
        for (int ni = 0; ni < 4; ni++)
#pragma unroll
            for (int q = 0; q < 4; q++) acc[mi][ni][q] = 0.f;

    const uint32_t sm0 = (uint32_t)__cvta_generic_to_shared(smc);

    auto load_tile = [&](int kt, int buf) {
        uint32_t Ab = sm0 + buf * SG_BUF_B;
        uint32_t Bh = Ab + SG_A_B;
        uint32_t Bl = Bh + SG_B_B;
        const float* xg = x + (size_t)(bm * 128) * DIN + kt;
        const __nv_bfloat16* whg = g_wxB_hi + (size_t)(bn * 128) * DIN + kt;
        const __nv_bfloat16* wlg = g_wxB_lo + (size_t)(bn * 128) * DIN + kt;
        // A: 128 rows x 32 floats = 1024 x 16B chunks, 2 per thread
#pragma unroll
        for (int q = 0; q < 2; q++) {
            int idx = tid + SG_THREADS * q;
            int arow = idx >> 3, ac4 = idx & 7;
            cpa16(Ab + (arow * SGA_STR + ac4 * 4) * 4, xg + (size_t)arow * DIN + ac4 * 4);
        }
        // B hi/lo: 128 rows x 32 bf16 = 512 x 16B chunks each, 1+1 per thread
        {
            int brow = tid >> 2, bc = tid & 3;   // bc*8 bf16 within row
            cpa16(Bh + (brow * SGB_STR + bc * 8) * 2, whg + (size_t)brow * DIN + bc * 8);
            cpa16(Bl + (brow * SGB_STR + bc * 8) * 2, wlg + (size_t)brow * DIN + bc * 8);
        }
    };

    load_tile(0, 0);
    asm volatile("cp.async.commit_group;");

    for (int t = 0; t < 32; t++) {
        if (t < 31) {
            load_tile((t + 1) * 32, (t + 1) & 1);
            asm volatile("cp.async.commit_group;");
            asm volatile("cp.async.wait_group 1;");
        } else {
            asm volatile("cp.async.wait_group 0;");
        }
        __syncthreads();

        const char* bufp = smc + (t & 1) * SG_BUF_B;
        const float* As = (const float*)bufp;
        const uint16_t* Bhp = (const uint16_t*)(bufp + SG_A_B);
        const uint16_t* Blp = (const uint16_t*)(bufp + SG_A_B + SG_B_B);

#pragma unroll
        for (int kf = 0; kf < 2; kf++) {
            const int k0 = kf * 16;
            // B fragments: b0 = k-pair (k0+2cq, +1) col n; b1 = +8
            uint32_t bh[4][2], bl[4][2];
#pragma unroll
            for (int ni = 0; ni < 4; ni++) {
                int n = wn * 32 + ni * 8 + r;
                bh[ni][0] = *(const uint32_t*)&Bhp[n * SGB_STR + k0 + 2 * cq];
                bh[ni][1] = *(const uint32_t*)&Bhp[n * SGB_STR + k0 + 2 * cq + 8];
                bl[ni][0] = *(const uint32_t*)&Blp[n * SGB_STR + k0 + 2 * cq];
                bl[ni][1] = *(const uint32_t*)&Blp[n * SGB_STR + k0 + 2 * cq + 8];
            }
#pragma unroll
            for (int mi = 0; mi < 2; mi++) {
                int rb = wm * 32 + mi * 16 + r;
                float2 p00 = *(const float2*)&As[rb * SGA_STR + k0 + 2 * cq];
                float2 p10 = *(const float2*)&As[(rb + 8) * SGA_STR + k0 + 2 * cq];
                float2 p01 = *(const float2*)&As[rb * SGA_STR + k0 + 2 * cq + 8];
                float2 p11 = *(const float2*)&As[(rb + 8) * SGA_STR + k0 + 2 * cq + 8];
                uint32_t ahi[4], alo[4];
                float2 ps[4] = {p00, p10, p01, p11};
#pragma unroll
                for (int q = 0; q < 4; q++) {
                    uint32_t h = packbf(ps[q].x, ps[q].y);
                    ahi[q] = h;
                    float he = __uint_as_float(h << 16);            // even elem as f32
                    float ho = __uint_as_float(h & 0xFFFF0000u);    // odd elem as f32
                    alo[q] = packbf(ps[q].x - he, ps[q].y - ho);
                }
#pragma unroll
                for (int ni = 0; ni < 4; ni++) {
                    mma_bf16(acc[mi][ni], ahi, bh[ni]);
                    mma_bf16(acc[mi][ni], ahi, bl[ni]);
                    mma_bf16(acc[mi][ni], alo, bh[ni]);
                }
            }
        }
        __syncthreads();
    }

    // epilogue: add bias, scatter to g_pre[t][g][b][h] (same C layout as k8)
#pragma unroll
    for (int ni = 0; ni < 4; ni++) {
        int n0 = bn * 128 + wn * 32 + ni * 8 + 2 * cq;
        int g = n0 >> 10, h = n0 & 1023;
        float2 bb = *(const float2*)(bx + n0);
#pragma unroll
        for (int mi = 0; mi < 2; mi++) {
            int m0 = bm * 128 + wm * 32 + mi * 16 + r;
            int t0 = m0 >> 5, b0 = m0 & 31;
            int m1 = m0 + 8;
            int t1 = m1 >> 5, b1 = m1 & 31;
            float2 o0 = make_float2(acc[mi][ni][0] + bb.x, acc[mi][ni][1] + bb.y);
            float2 o1 = make_float2(acc[mi][ni][2] + bb.x, acc[mi][ni][3] + bb.y);
            *(float2*)&g_pre[(((size_t)t0 * 4 + g) * 32 + b0) * 1024 + h] = o0;
            *(float2*)&g_pre[(((size_t)t1 * 4 + g) * 32 + b1) * 1024 + h] = o1;
        }
    }
}

// ---------------- software grid barrier ----------------
__device__ __forceinline__ void grid_bar() {
    __syncthreads();
    if (threadIdx.x == 0) {
        __threadfence();
        unsigned gen = g_gen;
        if (atomicAdd(&g_cnt, 1) == GRID_REC - 1) {
            g_cnt = 0;
            __threadfence();
            g_gen = gen + 1;
        } else {
            while (g_gen == gen) {}
        }
        __threadfence();
    }
    __syncthreads();
}

// ---------------- persistent recurrence (f32x2, k-paired) — unchanged (passing) ----------------
__global__ __launch_bounds__(REC_THREADS, 1) void rec_persist(float* __restrict__ out) {
    extern __shared__ float smem[];
    const int hs  = blockIdx.x;
    const int tid = threadIdx.x;
    const int w   = tid >> 5;
    const int ks  = w >> 2;
    const int whlp = w & 3;
    const int l   = tid & 31;
    const int hp  = l >> 4;
    const int b16 = l & 15;
    const int rg  = whlp * 2 + hp;
    const int b0  = b16, b1 = b16 + 16;
    const int rloc = whlp * 32 + l;

#pragma unroll
    for (int q = 0; q < 16; q++) {
        int i4 = tid + REC_THREADS * q;
        int lrr = i4 >> 8, kq = i4 & 255;
        *(float4*)&smem[lrr * WSTR + kq * 4] =
            *(const float4*)(g_whT + (size_t)(hs * 32 + lrr) * 1024 + kq * 4);
    }
    __syncthreads();

    float creg[2] = {0.f, 0.f};

    for (int t = 0; t < TLEN; t++) {
        const float* hc = g_h2[t & 1];

        float pg[4][2];
        if (ks == 0) {
            const float* pt = g_pre + (size_t)t * 131072 + hs * 8 + rg;
#pragma unroll
            for (int g = 0; g < 4; g++) {
                pg[g][0] = __ldcg(pt + g * 32768 + b0 * 1024);
                pg[g][1] = __ldcg(pt + g * 32768 + b1 * 1024);
            }
        }

        ull acc[4][2];
#pragma unroll
        for (int g = 0; g < 4; g++) { acc[g][0] = 0ull; acc[g][1] = 0ull; }

        float4 pf[4];
#pragma unroll
        for (int q = 0; q < 4; q++) {
            int f = tid + REC_THREADS * q;
            pf[q] = __ldcg((const float4*)(hc + (f >> 6) * 1024 + (f & 63) * 4));
        }

        for (int c = 0; c < 4; c++) {
#pragma unroll
            for (int q = 0; q < 4; q++) {
                int f = tid + REC_THREADS * q;
                *(float4*)&smem[SH_OFF + (f >> 6) * 260 + (f & 63) * 4] = pf[q];
            }
            __syncthreads();
            if (c < 3) {
#pragma unroll
                for (int q = 0; q < 4; q++) {
                    int f = tid + REC_THREADS * q;
                    pf[q] = __ldcg((const float4*)(hc + (f >> 6) * 1024 + (c + 1) * 256 + (f & 63) * 4));
                }
            }
            const float* wb  = &smem[rg * 4 * WSTR + c * 256 + ks * 64];
            const float* hr0 = &smem[SH_OFF + b0 * 260 + ks * 64];
            const float* hr1 = &smem[SH_OFF + b1 * 260 + ks * 64];
#pragma unroll
            for (int kk = 0; kk < 64; kk += 4) {
                ulonglong2 H0 = *(const ulonglong2*)(hr0 + kk);
                ulonglong2 H1 = *(const ulonglong2*)(hr1 + kk);
#pragma unroll
                for (int g = 0; g < 4; g++) {
                    ulonglong2 W = *(const ulonglong2*)(wb + g * WSTR + kk);
                    ffma2(acc[g][0], W.x, H0.x);
                    ffma2(acc[g][0], W.y, H0.y);
                    ffma2(acc[g][1], W.x, H1.x);
                    ffma2(acc[g][1], W.y, H1.y);
                }
            }
            __syncthreads();
        }

        float s[4][2];
#pragma unroll
        for (int g = 0; g < 4; g++) {
            float2 p0 = u2f(acc[g][0]); s[g][0] = p0.x + p0.y;
            float2 p1 = u2f(acc[g][1]); s[g][1] = p1.x + p1.y;
        }

        if (ks > 0) {
            float4* dst = (float4*)&smem[SRED_OFF + ((ks - 1) * 128 + rloc) * 8];
            dst[0] = make_float4(s[0][0], s[1][0], s[2][0], s[3][0]);
            dst[1] = make_float4(s[0][1], s[1][1], s[2][1], s[3][1]);
        }
        __syncthreads();

        if (ks == 0) {
#pragma unroll
            for (int q = 0; q < 3; q++) {
                const float4* src = (const float4*)&smem[SRED_OFF + (q * 128 + rloc) * 8];
                float4 v0 = src[0], v1 = src[1];
                s[0][0] += v0.x; s[1][0] += v0.y; s[2][0] += v0.z; s[3][0] += v0.w;
                s[0][1] += v1.x; s[1][1] += v1.y; s[2][1] += v1.z; s[3][1] += v1.w;
            }
#pragma unroll
            for (int j = 0; j < 2; j++) {
                float g0 = s[0][j] + pg[0][j];
                float g1 = s[1][j] + pg[1][j];
                float g2 = s[2][j] + pg[2][j];
                float g3 = s[3][j] + pg[3][j];
                float f = 1.f / (1.f + __expf(-g0));
                float i = 1.f / (1.f + __expf(-g1));
                float o = 1.f / (1.f + __expf(-g2));
                creg[j] = i * tanhf(g3) + f * creg[j];
                float hn = o * tanhf(creg[j]);
                int b = (j == 0) ? b0 : b1;
                int pidx = b * 1024 + hs * 8 + rg;
                g_h2[(t + 1) & 1][pidx] = hn;
                out[(size_t)t * (BATCH * HID) + pidx] = hn;
            }
        }

        grid_bar();
    }
}

// ---------------- launch: 4 graph nodes ----------------
extern "C" void kernel_launch(void* const* d_in, const int* in_sizes, int n_in,
                              void* d_out, int out_size) {
    const float* x  = (const float*)d_in[0];   // [500][32][1024]
    const float* wx = (const float*)d_in[1];   // [4][4][256][256]
    const float* wh = (const float*)d_in[2];   // [4][4][256][256]
    const float* bx = (const float*)d_in[3];   // [4][1024]
    float* out = (float*)d_out;                // [500][32][1024]

    cudaFuncSetAttribute(sgemm_pre_tc, cudaFuncAttributeMaxDynamicSharedMemorySize, SG_SMEM_BYTES);
    cudaFuncSetAttribute(rec_persist, cudaFuncAttributeMaxDynamicSharedMemorySize, SMEM_BYTES);

    expand_weights<<<32768, 256>>>(wx, wh);
    zero_state<<<128, 256>>>();
    sgemm_pre_tc<<<dim3(32, 125), SG_THREADS, SG_SMEM_BYTES>>>(x, bx);
    rec_persist<<<GRID_REC, REC_THREADS, SMEM_BYTES>>>(out);
}

// round 16
// speedup vs baseline: 1.1858x; 1.0869x over previous
#include <cuda_runtime.h>
#include <cuda_fp16.h>
#include <math.h>
#include <stdint.h>

#define TLEN  500
#define BATCH 32
#define DIN   1024
#define HID   1024
#define NT    4096      // 4 gates * HID
#define GRID_REC 128
#define REC_THREADS 512

// ---------------- rec_persist smem layout (floats) ----------------
#define WSTR  1028
#define SW_F  (32 * WSTR)
#define SH_F  (32 * 260)
#define SRED_F (3 * 128 * 8)
#define SH_OFF  SW_F
#define SRED_OFF (SW_F + SH_F)
#define SMEM_BYTES ((SW_F + SH_F + SRED_F) * 4)

// ---------------- sgemm smem layout (fp16, stride 40) ----------------
#define SG_STR  40                       // row stride in fp16 (banks 20r+cq all distinct)
#define SG_ARR_B (128 * SG_STR * 2)      // 10240 B per array (128 rows x 32 fp16)
#define SG_BUF_B (3 * SG_ARR_B)          // A_hi, A_lo, B = 30720 B
#define SG_SMEM_BYTES (2 * SG_BUF_B)     // 61440 B double-buffered
#define SG_THREADS 512

typedef unsigned long long ull;

__device__ __forceinline__ void ffma2(ull& d, ull a, ull b) {
    asm("fma.rn.f32x2 %0, %1, %2, %0;" : "+l"(d) : "l"(a), "l"(b));
}
__device__ __forceinline__ float2 u2f(ull u) {
    float2 r; asm("mov.b64 {%0,%1}, %2;" : "=f"(r.x), "=f"(r.y) : "l"(u)); return r;
}
__device__ __forceinline__ void mma_f16(float* c, const uint32_t* a, const uint32_t* b) {
    asm("mma.sync.aligned.m16n8k16.row.col.f32.f16.f16.f32 "
        "{%0,%1,%2,%3},{%4,%5,%6,%7},{%8,%9},{%0,%1,%2,%3};"
        : "+f"(c[0]), "+f"(c[1]), "+f"(c[2]), "+f"(c[3])
        : "r"(a[0]), "r"(a[1]), "r"(a[2]), "r"(a[3]), "r"(b[0]), "r"(b[1]));
}
__device__ __forceinline__ void cpa16(uint32_t saddr, const void* g) {
    asm volatile("cp.async.cg.shared.global [%0], [%1], 16;" :: "r"(saddr), "l"(g));
}

// ---------------- device-global scratch ----------------
__device__ __align__(16) __half g_x_hi[(size_t)TLEN * BATCH * DIN];   // 32 MB
__device__ __align__(16) __half g_x_lo[(size_t)TLEN * BATCH * DIN];   // 32 MB
__device__ __align__(16) __half g_wxB_h[(size_t)NT * DIN];            // [n][d] fp16, 8 MB
__device__ __align__(16) float g_whT[(size_t)NT * HID];               // [(h*4+g)][d] 16 MB
__device__ __align__(16) float g_pre[(size_t)TLEN * 4 * BATCH * HID]; // [t][g][b][h] 262 MB
__device__ __align__(16) float g_h2[2][BATCH * HID];
__device__ volatile unsigned g_gen;
__device__ unsigned g_cnt;

// quaternion cat tables
__constant__ int   c_qidx[16] = {0,1,2,3,  1,0,3,2,  2,3,0,1,  3,2,1,0};
__constant__ float c_qsgn[16] = { 1.f, 1.f, 1.f, 1.f,
                                 -1.f, 1.f, 1.f,-1.f,
                                 -1.f,-1.f, 1.f, 1.f,
                                 -1.f, 1.f,-1.f, 1.f};

// ---------------- weight expansion (wx -> fp16 [n][d]; wh -> fp32 rows) ----------------
__global__ void expand_weights(const float* __restrict__ wx, const float* __restrict__ wh) {
    int i = blockIdx.x * 256 + threadIdx.x;
    int half = i >> 22;
    int o = i & 4194303;
    if (half == 0) {
        int n = o >> 10, d = o & 1023;
        int g = n >> 10, ho = n & 1023;
        int e = ho >> 8, hh = ho & 255;
        int c = d >> 8,  dd = d & 255;
        int q = c * 4 + e;
        float v = c_qsgn[q] * wx[((g * 4 + c_qidx[q]) * 256 + dd) * 256 + hh];
        g_wxB_h[o] = __float2half_rn(v);
    } else {
        int h = o >> 12, g = (o >> 10) & 3, d = o & 1023;
        int e = h >> 8, hh = h & 255;
        int c = d >> 8, dd = d & 255;
        int q = c * 4 + e;
        g_whT[o] = c_qsgn[q] * wh[((g * 4 + c_qidx[q]) * 256 + dd) * 256 + hh];
    }
}

__global__ void x_split(const float* __restrict__ x) {
    int i = blockIdx.x * 256 + threadIdx.x;    // exactly covers 16,384,000
    float v = x[i];
    __half h = __float2half_rn(v);
    g_x_hi[i] = h;
    g_x_lo[i] = __float2half_rn(v - __half2float(h));
}

__global__ void zero_state() {
    int i = blockIdx.x * 256 + threadIdx.x;
    if (i < BATCH * HID) g_h2[0][i] = 0.f;
}

// ---------------- input GEMM (fp16 2-pass, mma.m16n8k16), 512 threads ----------------
// Block 128(m)x128(n), K-step 32, 16 warps each m32xn32 (2 mi x 4 ni).
// A = x split hi/lo (pre-split fp16); B = weights fp16 (single).
__global__ __launch_bounds__(SG_THREADS) void sgemm_pre_tc(const float* __restrict__ bx) {
    extern __shared__ char smc[];
    const int bn = blockIdx.x;      // 0..31
    const int bm = blockIdx.y;      // 0..124
    const int tid = threadIdx.x;
    const int lane = tid & 31;
    const int wid = tid >> 5;       // 0..15
    const int wm = wid & 3;         // m quadrant of 32
    const int wn = wid >> 2;        // n quadrant of 32
    const int r  = lane >> 2;       // 0..7
    const int cq = lane & 3;        // 0..3

    float acc[2][4][4];
#pragma unroll
    for (int mi = 0; mi < 2; mi++)
#pragma unroll
        for (int ni = 0; ni < 4; ni++)
#pragma unroll
            for (int q = 0; q < 4; q++) acc[mi][ni][q] = 0.f;

    const uint32_t sm0 = (uint32_t)__cvta_generic_to_shared(smc);

    // loader: 3 arrays x 128 rows x 64B (= 4 x 16B per row); 512 chunks/array, 1/thread
    auto load_tile = [&](int kt, int buf) {
        uint32_t Ah = sm0 + buf * SG_BUF_B;
        uint32_t Al = Ah + SG_ARR_B;
        uint32_t Bh = Al + SG_ARR_B;
        const __half* a0 = g_x_hi + (size_t)(bm * 128) * DIN + kt;
        const __half* a1 = g_x_lo + (size_t)(bm * 128) * DIN + kt;
        const __half* b0 = g_wxB_h + (size_t)(bn * 128) * DIN + kt;
        int row = tid >> 2, ch = tid & 3;
        uint32_t so = (row * SG_STR + ch * 8) * 2;
        size_t go = (size_t)row * DIN + ch * 8;
        cpa16(Ah + so, a0 + go);
        cpa16(Al + so, a1 + go);
        cpa16(Bh + so, b0 + go);
    };

    load_tile(0, 0);
    asm volatile("cp.async.commit_group;");

    for (int t = 0; t < 32; t++) {
        if (t < 31) {
            load_tile((t + 1) * 32, (t + 1) & 1);
            asm volatile("cp.async.commit_group;");
            asm volatile("cp.async.wait_group 1;");
        } else {
            asm volatile("cp.async.wait_group 0;");
        }
        __syncthreads();

        const char* bufp = smc + (t & 1) * SG_BUF_B;
        const uint16_t* Ahp = (const uint16_t*)bufp;
        const uint16_t* Alp = (const uint16_t*)(bufp + SG_ARR_B);
        const uint16_t* Bp  = (const uint16_t*)(bufp + 2 * SG_ARR_B);

#pragma unroll
        for (int kf = 0; kf < 2; kf++) {
            const int k0 = kf * 16;
            uint32_t bfr[4][2];
#pragma unroll
            for (int ni = 0; ni < 4; ni++) {
                int n = wn * 32 + ni * 8 + r;
                bfr[ni][0] = *(const uint32_t*)&Bp[n * SG_STR + k0 + 2 * cq];
                bfr[ni][1] = *(const uint32_t*)&Bp[n * SG_STR + k0 + 2 * cq + 8];
            }
#pragma unroll
            for (int mi = 0; mi < 2; mi++) {
                int rb = wm * 32 + mi * 16 + r;
                uint32_t ahi[4], alo[4];
                ahi[0] = *(const uint32_t*)&Ahp[rb * SG_STR + k0 + 2 * cq];
                ahi[1] = *(const uint32_t*)&Ahp[(rb + 8) * SG_STR + k0 + 2 * cq];
                ahi[2] = *(const uint32_t*)&Ahp[rb * SG_STR + k0 + 2 * cq + 8];
                ahi[3] = *(const uint32_t*)&Ahp[(rb + 8) * SG_STR + k0 + 2 * cq + 8];
                alo[0] = *(const uint32_t*)&Alp[rb * SG_STR + k0 + 2 * cq];
                alo[1] = *(const uint32_t*)&Alp[(rb + 8) * SG_STR + k0 + 2 * cq];
                alo[2] = *(const uint32_t*)&Alp[rb * SG_STR + k0 + 2 * cq + 8];
                alo[3] = *(const uint32_t*)&Alp[(rb + 8) * SG_STR + k0 + 2 * cq + 8];
#pragma unroll
                for (int ni = 0; ni < 4; ni++) {
                    mma_f16(acc[mi][ni], ahi, bfr[ni]);
                    mma_f16(acc[mi][ni], alo, bfr[ni]);
                }
            }
        }
        __syncthreads();
    }

    // epilogue: add bias, scatter to g_pre[t][g][b][h]
#pragma unroll
    for (int ni = 0; ni < 4; ni++) {
        int n0 = bn * 128 + wn * 32 + ni * 8 + 2 * cq;
        int g = n0 >> 10, h = n0 & 1023;
        float2 bb = *(const float2*)(bx + n0);
#pragma unroll
        for (int mi = 0; mi < 2; mi++) {
            int m0 = bm * 128 + wm * 32 + mi * 16 + r;
            int t0 = m0 >> 5, b0 = m0 & 31;
            int m1 = m0 + 8;
            int t1 = m1 >> 5, b1 = m1 & 31;
            float2 o0 = make_float2(acc[mi][ni][0] + bb.x, acc[mi][ni][1] + bb.y);
            float2 o1 = make_float2(acc[mi][ni][2] + bb.x, acc[mi][ni][3] + bb.y);
            *(float2*)&g_pre[(((size_t)t0 * 4 + g) * 32 + b0) * 1024 + h] = o0;
            *(float2*)&g_pre[(((size_t)t1 * 4 + g) * 32 + b1) * 1024 + h] = o1;
        }
    }
}

// ---------------- software grid barrier ----------------
__device__ __forceinline__ void grid_bar() {
    __syncthreads();
    if (threadIdx.x == 0) {
        __threadfence();
        unsigned gen = g_gen;
        if (atomicAdd(&g_cnt, 1) == GRID_REC - 1) {
            g_cnt = 0;
            __threadfence();
            g_gen = gen + 1;
        } else {
            while (g_gen == gen) {}
        }
        __threadfence();
    }
    __syncthreads();
}

// ---------------- persistent recurrence (f32x2, k-paired) — unchanged (passing) ----------------
__global__ __launch_bounds__(REC_THREADS, 1) void rec_persist(float* __restrict__ out) {
    extern __shared__ float smem[];
    const int hs  = blockIdx.x;
    const int tid = threadIdx.x;
    const int w   = tid >> 5;
    const int ks  = w >> 2;
    const int whlp = w & 3;
    const int l   = tid & 31;
    const int hp  = l >> 4;
    const int b16 = l & 15;
    const int rg  = whlp * 2 + hp;
    const int b0  = b16, b1 = b16 + 16;
    const int rloc = whlp * 32 + l;

#pragma unroll
    for (int q = 0; q < 16; q++) {
        int i4 = tid + REC_THREADS * q;
        int lrr = i4 >> 8, kq = i4 & 255;
        *(float4*)&smem[lrr * WSTR + kq * 4] =
            *(const float4*)(g_whT + (size_t)(hs * 32 + lrr) * 1024 + kq * 4);
    }
    __syncthreads();

    float creg[2] = {0.f, 0.f};

    for (int t = 0; t < TLEN; t++) {
        const float* hc = g_h2[t & 1];

        float pg[4][2];
        if (ks == 0) {
            const float* pt = g_pre + (size_t)t * 131072 + hs * 8 + rg;
#pragma unroll
            for (int g = 0; g < 4; g++) {
                pg[g][0] = __ldcg(pt + g * 32768 + b0 * 1024);
                pg[g][1] = __ldcg(pt + g * 32768 + b1 * 1024);
            }
        }

        ull acc[4][2];
#pragma unroll
        for (int g = 0; g < 4; g++) { acc[g][0] = 0ull; acc[g][1] = 0ull; }

        float4 pf[4];
#pragma unroll
        for (int q = 0; q < 4; q++) {
            int f = tid + REC_THREADS * q;
            pf[q] = __ldcg((const float4*)(hc + (f >> 6) * 1024 + (f & 63) * 4));
        }

        for (int c = 0; c < 4; c++) {
#pragma unroll
            for (int q = 0; q < 4; q++) {
                int f = tid + REC_THREADS * q;
                *(float4*)&smem[SH_OFF + (f >> 6) * 260 + (f & 63) * 4] = pf[q];
            }
            __syncthreads();
            if (c < 3) {
#pragma unroll
                for (int q = 0; q < 4; q++) {
                    int f = tid + REC_THREADS * q;
                    pf[q] = __ldcg((const float4*)(hc + (f >> 6) * 1024 + (c + 1) * 256 + (f & 63) * 4));
                }
            }
            const float* wb  = &smem[rg * 4 * WSTR + c * 256 + ks * 64];
            const float* hr0 = &smem[SH_OFF + b0 * 260 + ks * 64];
            const float* hr1 = &smem[SH_OFF + b1 * 260 + ks * 64];
#pragma unroll
            for (int kk = 0; kk < 64; kk += 4) {
                ulonglong2 H0 = *(const ulonglong2*)(hr0 + kk);
                ulonglong2 H1 = *(const ulonglong2*)(hr1 + kk);
#pragma unroll
                for (int g = 0; g < 4; g++) {
                    ulonglong2 W = *(const ulonglong2*)(wb + g * WSTR + kk);
                    ffma2(acc[g][0], W.x, H0.x);
                    ffma2(acc[g][0], W.y, H0.y);
                    ffma2(acc[g][1], W.x, H1.x);
                    ffma2(acc[g][1], W.y, H1.y);
                }
            }
            __syncthreads();
        }

        float s[4][2];
#pragma unroll
        for (int g = 0; g < 4; g++) {
            float2 p0 = u2f(acc[g][0]); s[g][0] = p0.x + p0.y;
            float2 p1 = u2f(acc[g][1]); s[g][1] = p1.x + p1.y;
        }

        if (ks > 0) {
            float4* dst = (float4*)&smem[SRED_OFF + ((ks - 1) * 128 + rloc) * 8];
            dst[0] = make_float4(s[0][0], s[1][0], s[2][0], s[3][0]);
            dst[1] = make_float4(s[0][1], s[1][1], s[2][1], s[3][1]);
        }
        __syncthreads();

        if (ks == 0) {
#pragma unroll
            for (int q = 0; q < 3; q++) {
                const float4* src = (const float4*)&smem[SRED_OFF + (q * 128 + rloc) * 8];
                float4 v0 = src[0], v1 = src[1];
                s[0][0] += v0.x; s[1][0] += v0.y; s[2][0] += v0.z; s[3][0] += v0.w;
                s[0][1] += v1.x; s[1][1] += v1.y; s[2][1] += v1.z; s[3][1] += v1.w;
            }
#pragma unroll
            for (int j = 0; j < 2; j++) {
                float g0 = s[0][j] + pg[0][j];
                float g1 = s[1][j] + pg[1][j];
                float g2 = s[2][j] + pg[2][j];
                float g3 = s[3][j] + pg[3][j];
                float f = 1.f / (1.f + __expf(-g0));
                float i = 1.f / (1.f + __expf(-g1));
                float o = 1.f / (1.f + __expf(-g2));
                creg[j] = i * tanhf(g3) + f * creg[j];
                float hn = o * tanhf(creg[j]);
                int b = (j == 0) ? b0 : b1;
                int pidx = b * 1024 + hs * 8 + rg;
                g_h2[(t + 1) & 1][pidx] = hn;
                out[(size_t)t * (BATCH * HID) + pidx] = hn;
            }
        }

        grid_bar();
    }
}

// ---------------- launch: 5 graph nodes ----------------
extern "C" void kernel_launch(void* const* d_in, const int* in_sizes, int n_in,
                              void* d_out, int out_size) {
    const float* x  = (const float*)d_in[0];   // [500][32][1024]
    const float* wx = (const float*)d_in[1];   // [4][4][256][256]
    const float* wh = (const float*)d_in[2];   // [4][4][256][256]
    const float* bx = (const float*)d_in[3];   // [4][1024]
    float* out = (float*)d_out;                // [500][32][1024]

    cudaFuncSetAttribute(sgemm_pre_tc, cudaFuncAttributeMaxDynamicSharedMemorySize, SG_SMEM_BYTES);
    cudaFuncSetAttribute(rec_persist, cudaFuncAttributeMaxDynamicSharedMemorySize, SMEM_BYTES);

    expand_weights<<<32768, 256>>>(wx, wh);
    x_split<<<64000, 256>>>(x);
    zero_state<<<128, 256>>>();
    sgemm_pre_tc<<<dim3(32, 125), SG_THREADS, SG_SMEM_BYTES>>>(bx);
    rec_persist<<<GRID_REC, REC_THREADS, SMEM_BYTES>>>(out);
}